// round 12
// baseline (speedup 1.0000x reference)
#include <cuda_runtime.h>

#define NATOM 384
#define NB 8
#define KNBR 383
#define NT 4
#define M0 25
#define M1 50
#define M2 100
#define ET 40
#define ER 8
#define EG 5
#define TPB 128
#define HST 40

__device__ int g_perm[NATOM * KNBR];
__device__ int g_boff[NATOM * NT];

__global__ void prep_kernel(const int* __restrict__ types) {
    __shared__ int ts[NATOM];
    int t = threadIdx.x;
    ts[t] = types[t];
    __syncthreads();
    int cnt[NT] = {0, 0, 0, 0};
    for (int j = 0; j < NATOM; j++)
        if (j != t) cnt[ts[j]]++;
    int off[NT];
    off[0] = 0;
    for (int c = 1; c < NT; c++) off[c] = off[c - 1] + cnt[c - 1];
    for (int c = 0; c < NT; c++) g_boff[t * NT + c] = off[c];
    for (int j = 0; j < NATOM; j++)
        if (j != t) {
            int c = ts[j];
            g_perm[t * KNBR + off[c]++] = j;
        }
}

__device__ __forceinline__ float tanh_m(float x) {
    float y;
    asm("tanh.approx.f32 %0, %1;" : "=f"(y) : "f"(x));
    return y;
}

// smem pool offsets (floats)
#define O_W2  0                      // W2r [M1][25][4] = 5000
#define O_W1  5000                   // W1r [M0][25][2] = 1250
#define O_H1  6252                   // h1 [M1][HST] = 2000
#define O_H0  8252                   // h0 [M0][HST] = 1000
#define O_AE  9252                   // aes [3][ET] = 120
#define O_XS  9372                   // xs [ET] = 40
#define O_W0  9412
#define O_B0  9440
#define O_B1  9468
#define O_B2  9520
#define POOL  9620                   // 38480 B  (6 CTAs x 38KB = 228KB exact)

__global__ __launch_bounds__(TPB, 6) void main_kernel(
    const float* __restrict__ coords, const int* __restrict__ types,
    const float* __restrict__ W0, const float* __restrict__ b0,
    const float* __restrict__ W1, const float* __restrict__ b1,
    const float* __restrict__ W2, const float* __restrict__ b2,
    float* __restrict__ out)
{
    __shared__ __align__(16) float P[POOL];
    float* const W2r = P + O_W2;
    float* const W1r = P + O_W1;
    float* const h1s = P + O_H1;
    float* const h0s = P + O_H0;
    float* const aes = P + O_AE;
    float* const xs  = P + O_XS;
    float* const W0s = P + O_W0;
    float* const b0s = P + O_B0;
    float* const b1r = P + O_B1;
    float* const b2r = P + O_B2;

    int t = threadIdx.x;
    int bid = blockIdx.x;
    int n = bid % NATOM;
    int b = bid / NATOM;
    int tc = __ldg(&types[n]);
    float cx = __ldg(&coords[(b * NATOM + n) * 3 + 0]);
    float cy = __ldg(&coords[(b * NATOM + n) * 3 + 1]);
    float cz = __ldg(&coords[(b * NATOM + n) * 3 + 2]);

    int gm = t % 25;
    int ge = t / 25;          // 0..4 for t<125
    int e0 = ge * ER;
    bool act = (t < 125);

    const float* const h0base = h0s + e0;
    const float* const h1base = h1s + e0;
    const float* const w1base = W1r + gm * 2;
    const float* const w2base = W2r + gm * 4;
    const float* const aeb = aes + e0;

    float Sp[4][3];
#pragma unroll
    for (int q = 0; q < 4; q++) { Sp[q][0] = 0.f; Sp[q][1] = 0.f; Sp[q][2] = 0.f; }

    for (int tn = 0; tn < NT; tn++) {
        __syncthreads();
        int idx = tc * NT + tn;
        for (int k = t; k < M1 * M2; k += TPB) {
            int j = k / M2, m = k - j * M2;
            int g = m % 25, q = m / 25;
            W2r[j * M2 + g * 4 + q] = W2[(size_t)idx * (M1 * M2) + k];
        }
        for (int k = t; k < M0 * M1; k += TPB) {
            int j = k / M1, m = k - j * M1;
            int g = m % 25, p = m / 25;
            W1r[j * M1 + g * 2 + p] = W1[(size_t)idx * (M0 * M1) + k];
        }
        if (t < M0) { W0s[t] = W0[idx * M0 + t]; b0s[t] = b0[idx * M0 + t]; }
        if (t < M1) { int g = t % 25, p = t / 25; b1r[g * 2 + p] = b1[idx * M1 + t]; }
        if (t < M2) { int g = t % 25, q = t / 25; b2r[g * 4 + q] = b2[idx * M2 + t]; }
        __syncthreads();

        int bs = g_boff[n * NT + tn];
        int be = (tn == NT - 1) ? KNBR : g_boff[n * NT + tn + 1];
        int cnt = be - bs;
        const int* pbase = g_perm + n * KNBR + bs;

        for (int t0 = 0; t0 < cnt; t0 += ET) {
            int rem = cnt - t0;
            bool glive = act && (e0 < rem);

            // ---- Stage 0a: geometry (40 threads) ----
            if (t < ET) {
                int gi = t0 + t;
                float x = 0.f, ax = 0.f, ay = 0.f, az = 0.f;
                if (gi < cnt) {
                    int j = __ldg(&pbase[gi]);
                    float rx = cx - __ldg(&coords[(b * NATOM + j) * 3 + 0]);
                    float ry = cy - __ldg(&coords[(b * NATOM + j) * 3 + 1]);
                    float rz = cz - __ldg(&coords[(b * NATOM + j) * 3 + 2]);
                    float d2 = rx * rx + ry * ry + rz * rz;
                    x = rsqrtf(d2);
                    float i2 = x * x;
                    ax = rx * i2; ay = ry * i2; az = rz * i2;
                }
                xs[t] = x;
                aes[0 * ET + t] = ax;
                aes[1 * ET + t] = ay;
                aes[2 * ET + t] = az;
            }
            __syncthreads();

            float h0v[ER];
            // ---- Stage 0b: layer0 ----
            if (glive) {
                float w0v = W0s[gm], b0v = b0s[gm];
                float4 xA = *(const float4*)(xs + e0);
                float4 xB = *(const float4*)(xs + e0 + 4);
                h0v[0] = tanh_m(fmaf(xA.x, w0v, b0v));
                h0v[1] = tanh_m(fmaf(xA.y, w0v, b0v));
                h0v[2] = tanh_m(fmaf(xA.z, w0v, b0v));
                h0v[3] = tanh_m(fmaf(xA.w, w0v, b0v));
                h0v[4] = tanh_m(fmaf(xB.x, w0v, b0v));
                h0v[5] = tanh_m(fmaf(xB.y, w0v, b0v));
                h0v[6] = tanh_m(fmaf(xB.z, w0v, b0v));
                h0v[7] = tanh_m(fmaf(xB.w, w0v, b0v));
                *(float4*)(h0s + gm * HST + e0) = make_float4(h0v[0], h0v[1], h0v[2], h0v[3]);
                *(float4*)(h0s + gm * HST + e0 + 4) = make_float4(h0v[4], h0v[5], h0v[6], h0v[7]);
            }
            __syncthreads();

            float h1v0[ER], h1v1[ER];
            // ---- Stage 1: 25->50 GEMM ----
            if (glive) {
                float acc0[ER], acc1[ER];
                float2 bb = *(const float2*)(b1r + gm * 2);
#pragma unroll
                for (int e = 0; e < ER; e++) { acc0[e] = bb.x; acc1[e] = bb.y; }
#pragma unroll
                for (int j = 0; j < M0; j++) {
                    float2 w = *(const float2*)(w1base + j * M1);
                    float4 A = *(const float4*)(h0base + j * HST);
                    float4 Bv = *(const float4*)(h0base + j * HST + 4);
                    acc0[0] = fmaf(w.x, A.x, acc0[0]); acc1[0] = fmaf(w.y, A.x, acc1[0]);
                    acc0[1] = fmaf(w.x, A.y, acc0[1]); acc1[1] = fmaf(w.y, A.y, acc1[1]);
                    acc0[2] = fmaf(w.x, A.z, acc0[2]); acc1[2] = fmaf(w.y, A.z, acc1[2]);
                    acc0[3] = fmaf(w.x, A.w, acc0[3]); acc1[3] = fmaf(w.y, A.w, acc1[3]);
                    acc0[4] = fmaf(w.x, Bv.x, acc0[4]); acc1[4] = fmaf(w.y, Bv.x, acc1[4]);
                    acc0[5] = fmaf(w.x, Bv.y, acc0[5]); acc1[5] = fmaf(w.y, Bv.y, acc1[5]);
                    acc0[6] = fmaf(w.x, Bv.z, acc0[6]); acc1[6] = fmaf(w.y, Bv.z, acc1[6]);
                    acc0[7] = fmaf(w.x, Bv.w, acc0[7]); acc1[7] = fmaf(w.y, Bv.w, acc1[7]);
                }
#pragma unroll
                for (int e = 0; e < ER; e++) {
                    h1v0[e] = tanh_m(acc0[e]) + h0v[e];
                    h1v1[e] = tanh_m(acc1[e]) + h0v[e];
                }
                *(float4*)(h1s + gm * HST + e0) = make_float4(h1v0[0], h1v0[1], h1v0[2], h1v0[3]);
                *(float4*)(h1s + gm * HST + e0 + 4) = make_float4(h1v0[4], h1v0[5], h1v0[6], h1v0[7]);
                *(float4*)(h1s + (gm + 25) * HST + e0) = make_float4(h1v1[0], h1v1[1], h1v1[2], h1v1[3]);
                *(float4*)(h1s + (gm + 25) * HST + e0 + 4) = make_float4(h1v1[4], h1v1[5], h1v1[6], h1v1[7]);
            }
            __syncthreads();

            // ---- Stage 2: 50->100 GEMM + combined epilogue ----
            if (glive) {
                float acc[4][ER];
                float4 bb = *(const float4*)(b2r + gm * 4);
#pragma unroll
                for (int e = 0; e < ER; e++) {
                    acc[0][e] = bb.x; acc[1][e] = bb.y; acc[2][e] = bb.z; acc[3][e] = bb.w;
                }
                const float* wp = w2base;
                const float* hp = h1base;
                for (int jb = 0; jb < 5; jb++) {
#pragma unroll
                    for (int u = 0; u < 10; u++) {
                        float4 w = *(const float4*)(wp + u * M2);
                        float4 A = *(const float4*)(hp + u * HST);
                        float4 Bv = *(const float4*)(hp + u * HST + 4);
                        acc[0][0] = fmaf(w.x, A.x, acc[0][0]); acc[1][0] = fmaf(w.y, A.x, acc[1][0]);
                        acc[2][0] = fmaf(w.z, A.x, acc[2][0]); acc[3][0] = fmaf(w.w, A.x, acc[3][0]);
                        acc[0][1] = fmaf(w.x, A.y, acc[0][1]); acc[1][1] = fmaf(w.y, A.y, acc[1][1]);
                        acc[2][1] = fmaf(w.z, A.y, acc[2][1]); acc[3][1] = fmaf(w.w, A.y, acc[3][1]);
                        acc[0][2] = fmaf(w.x, A.z, acc[0][2]); acc[1][2] = fmaf(w.y, A.z, acc[1][2]);
                        acc[2][2] = fmaf(w.z, A.z, acc[2][2]); acc[3][2] = fmaf(w.w, A.z, acc[3][2]);
                        acc[0][3] = fmaf(w.x, A.w, acc[0][3]); acc[1][3] = fmaf(w.y, A.w, acc[1][3]);
                        acc[2][3] = fmaf(w.z, A.w, acc[2][3]); acc[3][3] = fmaf(w.w, A.w, acc[3][3]);
                        acc[0][4] = fmaf(w.x, Bv.x, acc[0][4]); acc[1][4] = fmaf(w.y, Bv.x, acc[1][4]);
                        acc[2][4] = fmaf(w.z, Bv.x, acc[2][4]); acc[3][4] = fmaf(w.w, Bv.x, acc[3][4]);
                        acc[0][5] = fmaf(w.x, Bv.y, acc[0][5]); acc[1][5] = fmaf(w.y, Bv.y, acc[1][5]);
                        acc[2][5] = fmaf(w.z, Bv.y, acc[2][5]); acc[3][5] = fmaf(w.w, Bv.y, acc[3][5]);
                        acc[0][6] = fmaf(w.x, Bv.z, acc[0][6]); acc[1][6] = fmaf(w.y, Bv.z, acc[1][6]);
                        acc[2][6] = fmaf(w.z, Bv.z, acc[2][6]); acc[3][6] = fmaf(w.w, Bv.z, acc[3][6]);
                        acc[0][7] = fmaf(w.x, Bv.w, acc[0][7]); acc[1][7] = fmaf(w.y, Bv.w, acc[1][7]);
                        acc[2][7] = fmaf(w.z, Bv.w, acc[2][7]); acc[3][7] = fmaf(w.w, Bv.w, acc[3][7]);
                    }
                    wp += 10 * M2;
                    hp += 10 * HST;
                }
                float4 a0A = *(const float4*)(aeb + 0 * ET);
                float4 a0B = *(const float4*)(aeb + 0 * ET + 4);
                float4 a1A = *(const float4*)(aeb + 1 * ET);
                float4 a1B = *(const float4*)(aeb + 1 * ET + 4);
                float4 a2A = *(const float4*)(aeb + 2 * ET);
                float4 a2B = *(const float4*)(aeb + 2 * ET + 4);
                float a0[8] = {a0A.x, a0A.y, a0A.z, a0A.w, a0B.x, a0B.y, a0B.z, a0B.w};
                float a1[8] = {a1A.x, a1A.y, a1A.z, a1A.w, a1B.x, a1B.y, a1B.z, a1B.w};
                float a2[8] = {a2A.x, a2A.y, a2A.z, a2A.w, a2B.x, a2B.y, a2B.z, a2B.w};
#pragma unroll
                for (int e = 0; e < ER; e++) {
                    float v0 = tanh_m(acc[0][e]) + h1v0[e];
                    float v1 = tanh_m(acc[1][e]) + h1v1[e];
                    float v2 = tanh_m(acc[2][e]) + h1v0[e];
                    float v3 = tanh_m(acc[3][e]) + h1v1[e];
                    Sp[0][0] = fmaf(a0[e], v0, Sp[0][0]); Sp[0][1] = fmaf(a1[e], v0, Sp[0][1]); Sp[0][2] = fmaf(a2[e], v0, Sp[0][2]);
                    Sp[1][0] = fmaf(a0[e], v1, Sp[1][0]); Sp[1][1] = fmaf(a1[e], v1, Sp[1][1]); Sp[1][2] = fmaf(a2[e], v1, Sp[1][2]);
                    Sp[2][0] = fmaf(a0[e], v2, Sp[2][0]); Sp[2][1] = fmaf(a1[e], v2, Sp[2][1]); Sp[2][2] = fmaf(a2[e], v2, Sp[2][2]);
                    Sp[3][0] = fmaf(a0[e], v3, Sp[3][0]); Sp[3][1] = fmaf(a1[e], v3, Sp[3][1]); Sp[3][2] = fmaf(a2[e], v3, Sp[3][2]);
                }
            }
            __syncthreads();
        }
    }

    // ---- Final reduction ----
    float* const Sred = P;
    float* const Sfin = P + EG * M2 * 3;
    if (act) {
#pragma unroll
        for (int q = 0; q < 4; q++) {
            Sred[ge * (M2 * 3) + (gm + 25 * q) * 3 + 0] = Sp[q][0];
            Sred[ge * (M2 * 3) + (gm + 25 * q) * 3 + 1] = Sp[q][1];
            Sred[ge * (M2 * 3) + (gm + 25 * q) * 3 + 2] = Sp[q][2];
        }
    }
    __syncthreads();
    if (t < M2) {
        float s0 = 0.f, s1 = 0.f, s2 = 0.f;
#pragma unroll
        for (int g = 0; g < EG; g++) {
            s0 += Sred[g * (M2 * 3) + t * 3 + 0];
            s1 += Sred[g * (M2 * 3) + t * 3 + 1];
            s2 += Sred[g * (M2 * 3) + t * 3 + 2];
        }
        Sfin[t * 3 + 0] = s0; Sfin[t * 3 + 1] = s1; Sfin[t * 3 + 2] = s2;
    }
    __syncthreads();
    if (t < M2) {
        float s0 = Sfin[t * 3 + 0], s1 = Sfin[t * 3 + 1], s2 = Sfin[t * 3 + 2];
        float4 o;
        o.x = s0 * Sfin[0] + s1 * Sfin[1] + s2 * Sfin[2];
        o.y = s0 * Sfin[3] + s1 * Sfin[4] + s2 * Sfin[5];
        o.z = s0 * Sfin[6] + s1 * Sfin[7] + s2 * Sfin[8];
        o.w = s0 * Sfin[9] + s1 * Sfin[10] + s2 * Sfin[11];
        *(float4*)(out + (size_t)bid * (M2 * 4) + t * 4) = o;
    }
}

extern "C" void kernel_launch(void* const* d_in, const int* in_sizes, int n_in,
                              void* d_out, int out_size)
{
    const float* coords = (const float*)d_in[0];
    const int*   types  = (const int*)d_in[1];
    const float* W0     = (const float*)d_in[2];
    const float* b0     = (const float*)d_in[3];
    const float* W1     = (const float*)d_in[4];
    const float* b1     = (const float*)d_in[5];
    const float* W2     = (const float*)d_in[6];
    const float* b2     = (const float*)d_in[7];
    float* out = (float*)d_out;

    prep_kernel<<<1, NATOM>>>(types);
    main_kernel<<<NB * NATOM, TPB>>>(coords, types, W0, b0, W1, b1, W2, b2, out);
}

// round 13
// speedup vs baseline: 1.2599x; 1.2599x over previous
#include <cuda_runtime.h>

#define NATOM 384
#define NB 8
#define KNBR 383
#define NT 4
#define M0 25
#define M1 50
#define M2 100
#define ET 40
#define ER 8
#define EG 5
#define TPB 128
#define HST 44

__device__ int g_sorted[NATOM];   // atoms sorted by (type, index)
__device__ int g_ipos[NATOM];     // position of atom i in g_sorted
__device__ int g_start[NT + 1];   // global bucket starts (incl. self)

// Tiny prep: stable counting sort by type — pure ALU, no local memory.
__global__ void prep_kernel(const int* __restrict__ types) {
    __shared__ int ts[NATOM];
    int t = threadIdx.x;
    ts[t] = types[t];
    __syncthreads();
    int c = ts[t];
    int cnt0 = 0, cnt1 = 0, cnt2 = 0, cnt3 = 0, rank = 0;
    for (int j = 0; j < NATOM; j++) {
        int tj = ts[j];
        cnt0 += (tj == 0); cnt1 += (tj == 1); cnt2 += (tj == 2); cnt3 += (tj == 3);
        rank += (tj == c) && (j < t);
    }
    int s0 = 0, s1 = cnt0, s2 = cnt0 + cnt1, s3 = cnt0 + cnt1 + cnt2;
    int base = (c == 0) ? s0 : (c == 1) ? s1 : (c == 2) ? s2 : s3;
    int pos = base + rank;
    g_sorted[pos] = t;
    g_ipos[t] = pos;
    if (t == 0) {
        g_start[0] = 0; g_start[1] = s1; g_start[2] = s2; g_start[3] = s3;
        g_start[4] = NATOM;
    }
}

__device__ __forceinline__ float tanh_m(float x) {
    float y;
    asm("tanh.approx.f32 %0, %1;" : "=f"(y) : "f"(x));
    return y;
}

// smem pool offsets (floats)
#define O_W2  0                      // W2r [M1][25][4] = 5000
#define O_W1  5000                   // W1r [M0][25][2] = 1250
#define O_H1  6252                   // h1 [M1][HST] = 2200
#define O_H0  8452                   // h0 [M0][HST] = 1100
#define O_AE  9552                   // aes [3][ET] = 120
#define O_XS  9672                   // xs [ET] = 40
#define O_W0  9712
#define O_B0  9740
#define O_B1  9768
#define O_B2  9820
#define POOL  9920                   // 39680 B

__global__ __launch_bounds__(TPB, 5) void main_kernel(
    const float* __restrict__ coords, const int* __restrict__ types,
    const float* __restrict__ W0, const float* __restrict__ b0,
    const float* __restrict__ W1, const float* __restrict__ b1,
    const float* __restrict__ W2, const float* __restrict__ b2,
    float* __restrict__ out)
{
    __shared__ __align__(16) float P[POOL];
    float* const W2r = P + O_W2;
    float* const W1r = P + O_W1;
    float* const h1s = P + O_H1;
    float* const h0s = P + O_H0;
    float* const aes = P + O_AE;
    float* const xs  = P + O_XS;
    float* const W0s = P + O_W0;
    float* const b0s = P + O_B0;
    float* const b1r = P + O_B1;
    float* const b2r = P + O_B2;

    int t = threadIdx.x;
    int bid = blockIdx.x;
    int n = bid % NATOM;
    int b = bid / NATOM;
    int tc = __ldg(&types[n]);
    float cx = __ldg(&coords[(b * NATOM + n) * 3 + 0]);
    float cy = __ldg(&coords[(b * NATOM + n) * 3 + 1]);
    float cz = __ldg(&coords[(b * NATOM + n) * 3 + 2]);

    int ipos = __ldg(&g_ipos[n]);
    // neighbor-space bucket bounds: shift by 1 where global start exceeds ipos
    int nbs[NT + 1];
#pragma unroll
    for (int c = 0; c <= NT; c++) {
        int sg = __ldg(&g_start[c]);
        nbs[c] = sg - (sg > ipos ? 1 : 0);
    }

    int gm = t % 25;
    int ge = t / 25;          // 0..4 for t<125
    int e0 = ge * ER;
    bool act = (t < 125);

    const float* const h0base = h0s + e0;
    const float* const h1base = h1s + e0;
    const float* const w1base = W1r + gm * 2;
    const float* const w2base = W2r + gm * 4;
    const float* const aeb = aes + e0;

    float Sp[4][3];
#pragma unroll
    for (int q = 0; q < 4; q++) { Sp[q][0] = 0.f; Sp[q][1] = 0.f; Sp[q][2] = 0.f; }

    for (int tn = 0; tn < NT; tn++) {
        __syncthreads();
        int idx = tc * NT + tn;
        for (int k = t; k < M1 * M2; k += TPB) {
            int j = k / M2, m = k - j * M2;
            int g = m % 25, q = m / 25;
            W2r[j * M2 + g * 4 + q] = W2[(size_t)idx * (M1 * M2) + k];
        }
        for (int k = t; k < M0 * M1; k += TPB) {
            int j = k / M1, m = k - j * M1;
            int g = m % 25, p = m / 25;
            W1r[j * M1 + g * 2 + p] = W1[(size_t)idx * (M0 * M1) + k];
        }
        if (t < M0) { W0s[t] = W0[idx * M0 + t]; b0s[t] = b0[idx * M0 + t]; }
        if (t < M1) { int g = t % 25, p = t / 25; b1r[g * 2 + p] = b1[idx * M1 + t]; }
        if (t < M2) { int g = t % 25, q = t / 25; b2r[g * 4 + q] = b2[idx * M2 + t]; }
        __syncthreads();

        int bs = nbs[tn];
        int cnt = nbs[tn + 1] - bs;

        for (int t0 = 0; t0 < cnt; t0 += ET) {
            int rem = cnt - t0;
            bool glive = act && (e0 < rem);

            // ---- Stage 0a: geometry (40 threads) ----
            if (t < ET) {
                int gi = t0 + t;
                float x = 0.f, ax = 0.f, ay = 0.f, az = 0.f;
                if (gi < cnt) {
                    int k = bs + gi;
                    int j = __ldg(&g_sorted[k + (k >= ipos ? 1 : 0)]);
                    float rx = cx - __ldg(&coords[(b * NATOM + j) * 3 + 0]);
                    float ry = cy - __ldg(&coords[(b * NATOM + j) * 3 + 1]);
                    float rz = cz - __ldg(&coords[(b * NATOM + j) * 3 + 2]);
                    float d2 = rx * rx + ry * ry + rz * rz;
                    x = rsqrtf(d2);
                    float i2 = x * x;
                    ax = rx * i2; ay = ry * i2; az = rz * i2;
                }
                xs[t] = x;
                aes[0 * ET + t] = ax;
                aes[1 * ET + t] = ay;
                aes[2 * ET + t] = az;
            }
            __syncthreads();

            float h0v[ER];
            // ---- Stage 0b: layer0 ----
            if (glive) {
                float w0v = W0s[gm], b0v = b0s[gm];
                float4 xA = *(const float4*)(xs + e0);
                float4 xB = *(const float4*)(xs + e0 + 4);
                h0v[0] = tanh_m(fmaf(xA.x, w0v, b0v));
                h0v[1] = tanh_m(fmaf(xA.y, w0v, b0v));
                h0v[2] = tanh_m(fmaf(xA.z, w0v, b0v));
                h0v[3] = tanh_m(fmaf(xA.w, w0v, b0v));
                h0v[4] = tanh_m(fmaf(xB.x, w0v, b0v));
                h0v[5] = tanh_m(fmaf(xB.y, w0v, b0v));
                h0v[6] = tanh_m(fmaf(xB.z, w0v, b0v));
                h0v[7] = tanh_m(fmaf(xB.w, w0v, b0v));
                *(float4*)(h0s + gm * HST + e0) = make_float4(h0v[0], h0v[1], h0v[2], h0v[3]);
                *(float4*)(h0s + gm * HST + e0 + 4) = make_float4(h0v[4], h0v[5], h0v[6], h0v[7]);
            }
            __syncthreads();

            float h1v0[ER], h1v1[ER];
            // ---- Stage 1: 25->50 GEMM ----
            if (glive) {
                float acc0[ER], acc1[ER];
                float2 bb = *(const float2*)(b1r + gm * 2);
#pragma unroll
                for (int e = 0; e < ER; e++) { acc0[e] = bb.x; acc1[e] = bb.y; }
#pragma unroll
                for (int j = 0; j < M0; j++) {
                    float2 w = *(const float2*)(w1base + j * M1);
                    float4 A = *(const float4*)(h0base + j * HST);
                    float4 Bv = *(const float4*)(h0base + j * HST + 4);
                    acc0[0] = fmaf(w.x, A.x, acc0[0]); acc1[0] = fmaf(w.y, A.x, acc1[0]);
                    acc0[1] = fmaf(w.x, A.y, acc0[1]); acc1[1] = fmaf(w.y, A.y, acc1[1]);
                    acc0[2] = fmaf(w.x, A.z, acc0[2]); acc1[2] = fmaf(w.y, A.z, acc1[2]);
                    acc0[3] = fmaf(w.x, A.w, acc0[3]); acc1[3] = fmaf(w.y, A.w, acc1[3]);
                    acc0[4] = fmaf(w.x, Bv.x, acc0[4]); acc1[4] = fmaf(w.y, Bv.x, acc1[4]);
                    acc0[5] = fmaf(w.x, Bv.y, acc0[5]); acc1[5] = fmaf(w.y, Bv.y, acc1[5]);
                    acc0[6] = fmaf(w.x, Bv.z, acc0[6]); acc1[6] = fmaf(w.y, Bv.z, acc1[6]);
                    acc0[7] = fmaf(w.x, Bv.w, acc0[7]); acc1[7] = fmaf(w.y, Bv.w, acc1[7]);
                }
#pragma unroll
                for (int e = 0; e < ER; e++) {
                    h1v0[e] = tanh_m(acc0[e]) + h0v[e];
                    h1v1[e] = tanh_m(acc1[e]) + h0v[e];
                }
                *(float4*)(h1s + gm * HST + e0) = make_float4(h1v0[0], h1v0[1], h1v0[2], h1v0[3]);
                *(float4*)(h1s + gm * HST + e0 + 4) = make_float4(h1v0[4], h1v0[5], h1v0[6], h1v0[7]);
                *(float4*)(h1s + (gm + 25) * HST + e0) = make_float4(h1v1[0], h1v1[1], h1v1[2], h1v1[3]);
                *(float4*)(h1s + (gm + 25) * HST + e0 + 4) = make_float4(h1v1[4], h1v1[5], h1v1[6], h1v1[7]);
            }
            __syncthreads();

            // ---- Stage 2: 50->100 GEMM + combined epilogue ----
            if (glive) {
                float acc[4][ER];
                float4 bb = *(const float4*)(b2r + gm * 4);
#pragma unroll
                for (int e = 0; e < ER; e++) {
                    acc[0][e] = bb.x; acc[1][e] = bb.y; acc[2][e] = bb.z; acc[3][e] = bb.w;
                }
                const float* wp = w2base;
                const float* hp = h1base;
                for (int jb = 0; jb < 5; jb++) {
#pragma unroll
                    for (int u = 0; u < 10; u++) {
                        float4 w = *(const float4*)(wp + u * M2);
                        float4 A = *(const float4*)(hp + u * HST);
                        float4 Bv = *(const float4*)(hp + u * HST + 4);
                        acc[0][0] = fmaf(w.x, A.x, acc[0][0]); acc[1][0] = fmaf(w.y, A.x, acc[1][0]);
                        acc[2][0] = fmaf(w.z, A.x, acc[2][0]); acc[3][0] = fmaf(w.w, A.x, acc[3][0]);
                        acc[0][1] = fmaf(w.x, A.y, acc[0][1]); acc[1][1] = fmaf(w.y, A.y, acc[1][1]);
                        acc[2][1] = fmaf(w.z, A.y, acc[2][1]); acc[3][1] = fmaf(w.w, A.y, acc[3][1]);
                        acc[0][2] = fmaf(w.x, A.z, acc[0][2]); acc[1][2] = fmaf(w.y, A.z, acc[1][2]);
                        acc[2][2] = fmaf(w.z, A.z, acc[2][2]); acc[3][2] = fmaf(w.w, A.z, acc[3][2]);
                        acc[0][3] = fmaf(w.x, A.w, acc[0][3]); acc[1][3] = fmaf(w.y, A.w, acc[1][3]);
                        acc[2][3] = fmaf(w.z, A.w, acc[2][3]); acc[3][3] = fmaf(w.w, A.w, acc[3][3]);
                        acc[0][4] = fmaf(w.x, Bv.x, acc[0][4]); acc[1][4] = fmaf(w.y, Bv.x, acc[1][4]);
                        acc[2][4] = fmaf(w.z, Bv.x, acc[2][4]); acc[3][4] = fmaf(w.w, Bv.x, acc[3][4]);
                        acc[0][5] = fmaf(w.x, Bv.y, acc[0][5]); acc[1][5] = fmaf(w.y, Bv.y, acc[1][5]);
                        acc[2][5] = fmaf(w.z, Bv.y, acc[2][5]); acc[3][5] = fmaf(w.w, Bv.y, acc[3][5]);
                        acc[0][6] = fmaf(w.x, Bv.z, acc[0][6]); acc[1][6] = fmaf(w.y, Bv.z, acc[1][6]);
                        acc[2][6] = fmaf(w.z, Bv.z, acc[2][6]); acc[3][6] = fmaf(w.w, Bv.z, acc[3][6]);
                        acc[0][7] = fmaf(w.x, Bv.w, acc[0][7]); acc[1][7] = fmaf(w.y, Bv.w, acc[1][7]);
                        acc[2][7] = fmaf(w.z, Bv.w, acc[2][7]); acc[3][7] = fmaf(w.w, Bv.w, acc[3][7]);
                    }
                    wp += 10 * M2;
                    hp += 10 * HST;
                }
                float4 a0A = *(const float4*)(aeb + 0 * ET);
                float4 a0B = *(const float4*)(aeb + 0 * ET + 4);
                float4 a1A = *(const float4*)(aeb + 1 * ET);
                float4 a1B = *(const float4*)(aeb + 1 * ET + 4);
                float4 a2A = *(const float4*)(aeb + 2 * ET);
                float4 a2B = *(const float4*)(aeb + 2 * ET + 4);
                float a0[8] = {a0A.x, a0A.y, a0A.z, a0A.w, a0B.x, a0B.y, a0B.z, a0B.w};
                float a1[8] = {a1A.x, a1A.y, a1A.z, a1A.w, a1B.x, a1B.y, a1B.z, a1B.w};
                float a2[8] = {a2A.x, a2A.y, a2A.z, a2A.w, a2B.x, a2B.y, a2B.z, a2B.w};
#pragma unroll
                for (int e = 0; e < ER; e++) {
                    float v0 = tanh_m(acc[0][e]) + h1v0[e];
                    float v1 = tanh_m(acc[1][e]) + h1v1[e];
                    float v2 = tanh_m(acc[2][e]) + h1v0[e];
                    float v3 = tanh_m(acc[3][e]) + h1v1[e];
                    Sp[0][0] = fmaf(a0[e], v0, Sp[0][0]); Sp[0][1] = fmaf(a1[e], v0, Sp[0][1]); Sp[0][2] = fmaf(a2[e], v0, Sp[0][2]);
                    Sp[1][0] = fmaf(a0[e], v1, Sp[1][0]); Sp[1][1] = fmaf(a1[e], v1, Sp[1][1]); Sp[1][2] = fmaf(a2[e], v1, Sp[1][2]);
                    Sp[2][0] = fmaf(a0[e], v2, Sp[2][0]); Sp[2][1] = fmaf(a1[e], v2, Sp[2][1]); Sp[2][2] = fmaf(a2[e], v2, Sp[2][2]);
                    Sp[3][0] = fmaf(a0[e], v3, Sp[3][0]); Sp[3][1] = fmaf(a1[e], v3, Sp[3][1]); Sp[3][2] = fmaf(a2[e], v3, Sp[3][2]);
                }
            }
            __syncthreads();
        }
    }

    // ---- Final reduction ----
    float* const Sred = P;
    float* const Sfin = P + EG * M2 * 3;
    if (act) {
#pragma unroll
        for (int q = 0; q < 4; q++) {
            Sred[ge * (M2 * 3) + (gm + 25 * q) * 3 + 0] = Sp[q][0];
            Sred[ge * (M2 * 3) + (gm + 25 * q) * 3 + 1] = Sp[q][1];
            Sred[ge * (M2 * 3) + (gm + 25 * q) * 3 + 2] = Sp[q][2];
        }
    }
    __syncthreads();
    if (t < M2) {
        float s0 = 0.f, s1 = 0.f, s2 = 0.f;
#pragma unroll
        for (int g = 0; g < EG; g++) {
            s0 += Sred[g * (M2 * 3) + t * 3 + 0];
            s1 += Sred[g * (M2 * 3) + t * 3 + 1];
            s2 += Sred[g * (M2 * 3) + t * 3 + 2];
        }
        Sfin[t * 3 + 0] = s0; Sfin[t * 3 + 1] = s1; Sfin[t * 3 + 2] = s2;
    }
    __syncthreads();
    if (t < M2) {
        float s0 = Sfin[t * 3 + 0], s1 = Sfin[t * 3 + 1], s2 = Sfin[t * 3 + 2];
        float4 o;
        o.x = s0 * Sfin[0] + s1 * Sfin[1] + s2 * Sfin[2];
        o.y = s0 * Sfin[3] + s1 * Sfin[4] + s2 * Sfin[5];
        o.z = s0 * Sfin[6] + s1 * Sfin[7] + s2 * Sfin[8];
        o.w = s0 * Sfin[9] + s1 * Sfin[10] + s2 * Sfin[11];
        *(float4*)(out + (size_t)bid * (M2 * 4) + t * 4) = o;
    }
}

extern "C" void kernel_launch(void* const* d_in, const int* in_sizes, int n_in,
                              void* d_out, int out_size)
{
    const float* coords = (const float*)d_in[0];
    const int*   types  = (const int*)d_in[1];
    const float* W0     = (const float*)d_in[2];
    const float* b0     = (const float*)d_in[3];
    const float* W1     = (const float*)d_in[4];
    const float* b1     = (const float*)d_in[5];
    const float* W2     = (const float*)d_in[6];
    const float* b2     = (const float*)d_in[7];
    float* out = (float*)d_out;

    prep_kernel<<<1, NATOM>>>(types);
    main_kernel<<<NB * NATOM, TPB>>>(coords, types, W0, b0, W1, b1, W2, b2, out);
}

// round 14
// speedup vs baseline: 1.2641x; 1.0033x over previous
#include <cuda_runtime.h>

#define NATOM 384
#define NB 8
#define KNBR 383
#define NT 4
#define M0 25
#define M1 50
#define M2 100
#define ET 40
#define ER 8
#define EG 5
#define TPB 128
#define HST 44

__device__ int g_sorted[NATOM];
__device__ int g_ipos[NATOM];
__device__ int g_start[NT + 1];

__global__ void prep_kernel(const int* __restrict__ types) {
    __shared__ int ts[NATOM];
    int t = threadIdx.x;
    ts[t] = types[t];
    __syncthreads();
    int c = ts[t];
    int cnt0 = 0, cnt1 = 0, cnt2 = 0, cnt3 = 0, rank = 0;
    for (int j = 0; j < NATOM; j++) {
        int tj = ts[j];
        cnt0 += (tj == 0); cnt1 += (tj == 1); cnt2 += (tj == 2); cnt3 += (tj == 3);
        rank += (tj == c) && (j < t);
    }
    int s1 = cnt0, s2 = cnt0 + cnt1, s3 = cnt0 + cnt1 + cnt2;
    int base = (c == 0) ? 0 : (c == 1) ? s1 : (c == 2) ? s2 : s3;
    int pos = base + rank;
    g_sorted[pos] = t;
    g_ipos[t] = pos;
    if (t == 0) {
        g_start[0] = 0; g_start[1] = s1; g_start[2] = s2; g_start[3] = s3;
        g_start[4] = NATOM;
    }
}

__device__ __forceinline__ float tanh_m(float x) {
    float y;
    asm("tanh.approx.f32 %0, %1;" : "=f"(y) : "f"(x));
    return y;
}

// smem pool offsets (floats)
#define O_W2  0                      // W2r [M1][25][4] = 5000
#define O_W1  5000                   // W1r [M0][25][2] = 1250
#define O_H1  6252                   // h1 [M1][HST] = 2200
#define O_H0  8452                   // h0 [M0][HST] = 1100
#define O_AE  9552                   // aes [3][ET] = 120
#define O_XS  9672                   // xs [ET] = 40
#define O_W0  9712
#define O_B0  9740
#define O_B1  9768
#define O_B2  9820
#define POOL  9920                   // 39680 B

__global__ __launch_bounds__(TPB, 5) void main_kernel(
    const float* __restrict__ coords, const int* __restrict__ types,
    const float* __restrict__ W0, const float* __restrict__ b0,
    const float* __restrict__ W1, const float* __restrict__ b1,
    const float* __restrict__ W2, const float* __restrict__ b2,
    float* __restrict__ out)
{
    __shared__ __align__(16) float P[POOL];
    float* const W2r = P + O_W2;
    float* const W1r = P + O_W1;
    float* const h1s = P + O_H1;
    float* const h0s = P + O_H0;
    float* const aes = P + O_AE;
    float* const xs  = P + O_XS;
    float* const W0s = P + O_W0;
    float* const b0s = P + O_B0;
    float* const b1r = P + O_B1;
    float* const b2r = P + O_B2;

    int t = threadIdx.x;
    int bid = blockIdx.x;
    int n = bid % NATOM;
    int b = bid / NATOM;
    int tc = __ldg(&types[n]);
    float cx = __ldg(&coords[(b * NATOM + n) * 3 + 0]);
    float cy = __ldg(&coords[(b * NATOM + n) * 3 + 1]);
    float cz = __ldg(&coords[(b * NATOM + n) * 3 + 2]);

    int ipos = __ldg(&g_ipos[n]);
    int nbs[NT + 1];
#pragma unroll
    for (int c = 0; c <= NT; c++) {
        int sg = __ldg(&g_start[c]);
        nbs[c] = sg - (sg > ipos ? 1 : 0);
    }

    int gm = t % 25;
    int ge = t / 25;
    int e0 = ge * ER;
    bool act = (t < 125);

    const float* const h0base = h0s + e0;
    const float* const h1base = h1s + e0;
    const float* const w1base = W1r + gm * 2;
    const float* const w2base = W2r + gm * 4;
    const float* const aeb = aes + e0;

    // Precompute incremental staging maps (constant per thread).
    // W2: element k = t + i*128 of [50][100]; j = k/100, m = k%100, g = m%25, q = m/25.
    // Steps: k += 128 -> m += 28 (mod 100 -> j++ carry handled per-iter branchless).
    // W1: element k of [25][50]; k += 128 -> m += 28 (mod 50).
    float Sp[4][3];
#pragma unroll
    for (int q = 0; q < 4; q++) { Sp[q][0] = 0.f; Sp[q][1] = 0.f; Sp[q][2] = 0.f; }

    // initial decompositions (computed once; loop uses adds/compares only)
    int w2_j0 = t / M2, w2_m0 = t - w2_j0 * M2;
    int w1_j0 = t / M1, w1_m0 = t - w1_j0 * M1;

    for (int tn = 0; tn < NT; tn++) {
        __syncthreads();
        int idx = tc * NT + tn;
        const float* W2g = W2 + (size_t)idx * (M1 * M2);
        const float* W1g = W1 + (size_t)idx * (M0 * M1);

        // ---- W2 staging: 40 iterations exactly (5000/128 = 39.06) ----
        {
            int j = w2_j0, m = w2_m0;
#pragma unroll 8
            for (int i = 0; i < 40; i++) {
                int k = t + i * TPB;
                if (k < M1 * M2) {
                    int g = m % 25, q = m / 25;
                    W2r[j * M2 + g * 4 + q] = W2g[k];
                }
                m += TPB - M2;           // +28
                if (m >= M2) { m -= M2; j += 2; } else { j += 1; }
            }
        }
        // ---- W1 staging: 10 iterations (1250/128 = 9.77) ----
        {
            int j = w1_j0, m = w1_m0;
#pragma unroll
            for (int i = 0; i < 10; i++) {
                int k = t + i * TPB;
                if (k < M0 * M1) {
                    int g = m % 25, p = m / 25;
                    W1r[j * M1 + g * 2 + p] = W1g[k];
                }
                m += TPB - 2 * M1;       // +28 (mod 50 step: 128 = 2*50 + 28)
                if (m >= M1) { m -= M1; j += 3; } else { j += 2; }
            }
        }
        if (t < M0) { W0s[t] = W0[idx * M0 + t]; b0s[t] = b0[idx * M0 + t]; }
        if (t < M1) { int g = t % 25, p = t / 25; b1r[g * 2 + p] = b1[idx * M1 + t]; }
        if (t < M2) { int g = t % 25, q = t / 25; b2r[g * 4 + q] = b2[idx * M2 + t]; }
        __syncthreads();

        int bs = nbs[tn];
        int cnt = nbs[tn + 1] - bs;

        for (int t0 = 0; t0 < cnt; t0 += ET) {
            int rem = cnt - t0;
            bool glive = act && (e0 < rem);

            // ---- Stage 0a: geometry (40 threads) ----
            if (t < ET) {
                int gi = t0 + t;
                float x = 0.f, ax = 0.f, ay = 0.f, az = 0.f;
                if (gi < cnt) {
                    int k = bs + gi;
                    int j = __ldg(&g_sorted[k + (k >= ipos ? 1 : 0)]);
                    float rx = cx - __ldg(&coords[(b * NATOM + j) * 3 + 0]);
                    float ry = cy - __ldg(&coords[(b * NATOM + j) * 3 + 1]);
                    float rz = cz - __ldg(&coords[(b * NATOM + j) * 3 + 2]);
                    float d2 = rx * rx + ry * ry + rz * rz;
                    x = rsqrtf(d2);
                    float i2 = x * x;
                    ax = rx * i2; ay = ry * i2; az = rz * i2;
                }
                xs[t] = x;
                aes[0 * ET + t] = ax;
                aes[1 * ET + t] = ay;
                aes[2 * ET + t] = az;
            }
            __syncthreads();

            float h0v[ER];
            if (glive) {
                float w0v = W0s[gm], b0v = b0s[gm];
                float4 xA = *(const float4*)(xs + e0);
                float4 xB = *(const float4*)(xs + e0 + 4);
                h0v[0] = tanh_m(fmaf(xA.x, w0v, b0v));
                h0v[1] = tanh_m(fmaf(xA.y, w0v, b0v));
                h0v[2] = tanh_m(fmaf(xA.z, w0v, b0v));
                h0v[3] = tanh_m(fmaf(xA.w, w0v, b0v));
                h0v[4] = tanh_m(fmaf(xB.x, w0v, b0v));
                h0v[5] = tanh_m(fmaf(xB.y, w0v, b0v));
                h0v[6] = tanh_m(fmaf(xB.z, w0v, b0v));
                h0v[7] = tanh_m(fmaf(xB.w, w0v, b0v));
                *(float4*)(h0s + gm * HST + e0) = make_float4(h0v[0], h0v[1], h0v[2], h0v[3]);
                *(float4*)(h0s + gm * HST + e0 + 4) = make_float4(h0v[4], h0v[5], h0v[6], h0v[7]);
            }
            __syncthreads();

            float h1v0[ER], h1v1[ER];
            if (glive) {
                float acc0[ER], acc1[ER];
                float2 bb = *(const float2*)(b1r + gm * 2);
#pragma unroll
                for (int e = 0; e < ER; e++) { acc0[e] = bb.x; acc1[e] = bb.y; }
#pragma unroll
                for (int j = 0; j < M0; j++) {
                    float2 w = *(const float2*)(w1base + j * M1);
                    float4 A = *(const float4*)(h0base + j * HST);
                    float4 Bv = *(const float4*)(h0base + j * HST + 4);
                    acc0[0] = fmaf(w.x, A.x, acc0[0]); acc1[0] = fmaf(w.y, A.x, acc1[0]);
                    acc0[1] = fmaf(w.x, A.y, acc0[1]); acc1[1] = fmaf(w.y, A.y, acc1[1]);
                    acc0[2] = fmaf(w.x, A.z, acc0[2]); acc1[2] = fmaf(w.y, A.z, acc1[2]);
                    acc0[3] = fmaf(w.x, A.w, acc0[3]); acc1[3] = fmaf(w.y, A.w, acc1[3]);
                    acc0[4] = fmaf(w.x, Bv.x, acc0[4]); acc1[4] = fmaf(w.y, Bv.x, acc1[4]);
                    acc0[5] = fmaf(w.x, Bv.y, acc0[5]); acc1[5] = fmaf(w.y, Bv.y, acc1[5]);
                    acc0[6] = fmaf(w.x, Bv.z, acc0[6]); acc1[6] = fmaf(w.y, Bv.z, acc1[6]);
                    acc0[7] = fmaf(w.x, Bv.w, acc0[7]); acc1[7] = fmaf(w.y, Bv.w, acc1[7]);
                }
#pragma unroll
                for (int e = 0; e < ER; e++) {
                    h1v0[e] = tanh_m(acc0[e]) + h0v[e];
                    h1v1[e] = tanh_m(acc1[e]) + h0v[e];
                }
                *(float4*)(h1s + gm * HST + e0) = make_float4(h1v0[0], h1v0[1], h1v0[2], h1v0[3]);
                *(float4*)(h1s + gm * HST + e0 + 4) = make_float4(h1v0[4], h1v0[5], h1v0[6], h1v0[7]);
                *(float4*)(h1s + (gm + 25) * HST + e0) = make_float4(h1v1[0], h1v1[1], h1v1[2], h1v1[3]);
                *(float4*)(h1s + (gm + 25) * HST + e0 + 4) = make_float4(h1v1[4], h1v1[5], h1v1[6], h1v1[7]);
            }
            __syncthreads();

            if (glive) {
                float acc[4][ER];
                float4 bb = *(const float4*)(b2r + gm * 4);
#pragma unroll
                for (int e = 0; e < ER; e++) {
                    acc[0][e] = bb.x; acc[1][e] = bb.y; acc[2][e] = bb.z; acc[3][e] = bb.w;
                }
                const float* wp = w2base;
                const float* hp = h1base;
                for (int jb = 0; jb < 5; jb++) {
#pragma unroll
                    for (int u = 0; u < 10; u++) {
                        float4 w = *(const float4*)(wp + u * M2);
                        float4 A = *(const float4*)(hp + u * HST);
                        float4 Bv = *(const float4*)(hp + u * HST + 4);
                        acc[0][0] = fmaf(w.x, A.x, acc[0][0]); acc[1][0] = fmaf(w.y, A.x, acc[1][0]);
                        acc[2][0] = fmaf(w.z, A.x, acc[2][0]); acc[3][0] = fmaf(w.w, A.x, acc[3][0]);
                        acc[0][1] = fmaf(w.x, A.y, acc[0][1]); acc[1][1] = fmaf(w.y, A.y, acc[1][1]);
                        acc[2][1] = fmaf(w.z, A.y, acc[2][1]); acc[3][1] = fmaf(w.w, A.y, acc[3][1]);
                        acc[0][2] = fmaf(w.x, A.z, acc[0][2]); acc[1][2] = fmaf(w.y, A.z, acc[1][2]);
                        acc[2][2] = fmaf(w.z, A.z, acc[2][2]); acc[3][2] = fmaf(w.w, A.z, acc[3][2]);
                        acc[0][3] = fmaf(w.x, A.w, acc[0][3]); acc[1][3] = fmaf(w.y, A.w, acc[1][3]);
                        acc[2][3] = fmaf(w.z, A.w, acc[2][3]); acc[3][3] = fmaf(w.w, A.w, acc[3][3]);
                        acc[0][4] = fmaf(w.x, Bv.x, acc[0][4]); acc[1][4] = fmaf(w.y, Bv.x, acc[1][4]);
                        acc[2][4] = fmaf(w.z, Bv.x, acc[2][4]); acc[3][4] = fmaf(w.w, Bv.x, acc[3][4]);
                        acc[0][5] = fmaf(w.x, Bv.y, acc[0][5]); acc[1][5] = fmaf(w.y, Bv.y, acc[1][5]);
                        acc[2][5] = fmaf(w.z, Bv.y, acc[2][5]); acc[3][5] = fmaf(w.w, Bv.y, acc[3][5]);
                        acc[0][6] = fmaf(w.x, Bv.z, acc[0][6]); acc[1][6] = fmaf(w.y, Bv.z, acc[1][6]);
                        acc[2][6] = fmaf(w.z, Bv.z, acc[2][6]); acc[3][6] = fmaf(w.w, Bv.z, acc[3][6]);
                        acc[0][7] = fmaf(w.x, Bv.w, acc[0][7]); acc[1][7] = fmaf(w.y, Bv.w, acc[1][7]);
                        acc[2][7] = fmaf(w.z, Bv.w, acc[2][7]); acc[3][7] = fmaf(w.w, Bv.w, acc[3][7]);
                    }
                    wp += 10 * M2;
                    hp += 10 * HST;
                }
                float4 a0A = *(const float4*)(aeb + 0 * ET);
                float4 a0B = *(const float4*)(aeb + 0 * ET + 4);
                float4 a1A = *(const float4*)(aeb + 1 * ET);
                float4 a1B = *(const float4*)(aeb + 1 * ET + 4);
                float4 a2A = *(const float4*)(aeb + 2 * ET);
                float4 a2B = *(const float4*)(aeb + 2 * ET + 4);
                float a0[8] = {a0A.x, a0A.y, a0A.z, a0A.w, a0B.x, a0B.y, a0B.z, a0B.w};
                float a1[8] = {a1A.x, a1A.y, a1A.z, a1A.w, a1B.x, a1B.y, a1B.z, a1B.w};
                float a2[8] = {a2A.x, a2A.y, a2A.z, a2A.w, a2B.x, a2B.y, a2B.z, a2B.w};
#pragma unroll
                for (int e = 0; e < ER; e++) {
                    float v0 = tanh_m(acc[0][e]) + h1v0[e];
                    float v1 = tanh_m(acc[1][e]) + h1v1[e];
                    float v2 = tanh_m(acc[2][e]) + h1v0[e];
                    float v3 = tanh_m(acc[3][e]) + h1v1[e];
                    Sp[0][0] = fmaf(a0[e], v0, Sp[0][0]); Sp[0][1] = fmaf(a1[e], v0, Sp[0][1]); Sp[0][2] = fmaf(a2[e], v0, Sp[0][2]);
                    Sp[1][0] = fmaf(a0[e], v1, Sp[1][0]); Sp[1][1] = fmaf(a1[e], v1, Sp[1][1]); Sp[1][2] = fmaf(a2[e], v1, Sp[1][2]);
                    Sp[2][0] = fmaf(a0[e], v2, Sp[2][0]); Sp[2][1] = fmaf(a1[e], v2, Sp[2][1]); Sp[2][2] = fmaf(a2[e], v2, Sp[2][2]);
                    Sp[3][0] = fmaf(a0[e], v3, Sp[3][0]); Sp[3][1] = fmaf(a1[e], v3, Sp[3][1]); Sp[3][2] = fmaf(a2[e], v3, Sp[3][2]);
                }
            }
            __syncthreads();
        }
    }

    // ---- Final reduction ----
    float* const Sred = P;
    float* const Sfin = P + EG * M2 * 3;
    if (act) {
#pragma unroll
        for (int q = 0; q < 4; q++) {
            Sred[ge * (M2 * 3) + (gm + 25 * q) * 3 + 0] = Sp[q][0];
            Sred[ge * (M2 * 3) + (gm + 25 * q) * 3 + 1] = Sp[q][1];
            Sred[ge * (M2 * 3) + (gm + 25 * q) * 3 + 2] = Sp[q][2];
        }
    }
    __syncthreads();
    if (t < M2) {
        float s0 = 0.f, s1 = 0.f, s2 = 0.f;
#pragma unroll
        for (int g = 0; g < EG; g++) {
            s0 += Sred[g * (M2 * 3) + t * 3 + 0];
            s1 += Sred[g * (M2 * 3) + t * 3 + 1];
            s2 += Sred[g * (M2 * 3) + t * 3 + 2];
        }
        Sfin[t * 3 + 0] = s0; Sfin[t * 3 + 1] = s1; Sfin[t * 3 + 2] = s2;
    }
    __syncthreads();
    if (t < M2) {
        float s0 = Sfin[t * 3 + 0], s1 = Sfin[t * 3 + 1], s2 = Sfin[t * 3 + 2];
        float4 o;
        o.x = s0 * Sfin[0] + s1 * Sfin[1] + s2 * Sfin[2];
        o.y = s0 * Sfin[3] + s1 * Sfin[4] + s2 * Sfin[5];
        o.z = s0 * Sfin[6] + s1 * Sfin[7] + s2 * Sfin[8];
        o.w = s0 * Sfin[9] + s1 * Sfin[10] + s2 * Sfin[11];
        *(float4*)(out + (size_t)bid * (M2 * 4) + t * 4) = o;
    }
}

extern "C" void kernel_launch(void* const* d_in, const int* in_sizes, int n_in,
                              void* d_out, int out_size)
{
    const float* coords = (const float*)d_in[0];
    const int*   types  = (const int*)d_in[1];
    const float* W0     = (const float*)d_in[2];
    const float* b0     = (const float*)d_in[3];
    const float* W1     = (const float*)d_in[4];
    const float* b1     = (const float*)d_in[5];
    const float* W2     = (const float*)d_in[6];
    const float* b2     = (const float*)d_in[7];
    float* out = (float*)d_out;

    prep_kernel<<<1, NATOM>>>(types);
    main_kernel<<<NB * NATOM, TPB>>>(coords, types, W0, b0, W1, b1, W2, b2, out);
}

// round 15
// speedup vs baseline: 3.8531x; 3.0481x over previous
#include <cuda_runtime.h>
#include <math.h>

#define NATOM 384
#define NB 8
#define KNBR 383
#define NT 4
#define M0 25
#define M1 50
#define M2 100
#define TPB 128
#define KNOT 256
#define CWARP 0.25f

__device__ int g_sorted[NATOM];
__device__ int g_ipos[NATOM];
__device__ int g_start[NT + 1];
__device__ float g_table[16 * KNOT * M2];   // [pair][knot][m], 1.64 MB

// ---- tiny prep: stable counting sort by type ----
__global__ void prep_kernel(const int* __restrict__ types) {
    __shared__ int ts[NATOM];
    int t = threadIdx.x;
    ts[t] = types[t];
    __syncthreads();
    int c = ts[t];
    int cnt0 = 0, cnt1 = 0, cnt2 = 0, rank = 0;
    for (int j = 0; j < NATOM; j++) {
        int tj = ts[j];
        cnt0 += (tj == 0); cnt1 += (tj == 1); cnt2 += (tj == 2);
        rank += (tj == c) && (j < t);
    }
    int s1 = cnt0, s2 = cnt0 + cnt1, s3 = cnt0 + cnt1 + cnt2;
    int base = (c == 0) ? 0 : (c == 1) ? s1 : (c == 2) ? s2 : s3;
    int pos = base + rank;
    g_sorted[pos] = t;
    g_ipos[t] = pos;
    if (t == 0) {
        g_start[0] = 0; g_start[1] = s1; g_start[2] = s2; g_start[3] = s3;
        g_start[4] = NATOM;
    }
}

// ---- table build: one block per (pair, knot), 100 threads (one per m) ----
__global__ void build_kernel(
    const float* __restrict__ W0, const float* __restrict__ b0,
    const float* __restrict__ W1, const float* __restrict__ b1,
    const float* __restrict__ W2, const float* __restrict__ b2)
{
    int blk = blockIdx.x;
    int p = blk / KNOT;
    int i = blk % KNOT;
    int m = threadIdx.x;

    float u = (float)i / (float)(KNOT - 1);
    u = fminf(u, 0.9999f);
    float x = CWARP * u / (1.0f - u);

    __shared__ float h0[M0];
    __shared__ float h1[M1];

    if (m < M0)
        h0[m] = tanhf(x * W0[p * M0 + m] + b0[p * M0 + m]);
    __syncthreads();
    if (m < M1) {
        float acc = b1[p * M1 + m];
        for (int j = 0; j < M0; j++)
            acc = fmaf(h0[j], W1[p * (M0 * M1) + j * M1 + m], acc);
        h1[m] = tanhf(acc) + h0[m % M0];
    }
    __syncthreads();
    {
        float acc = b2[p * M2 + m];
        for (int j = 0; j < M1; j++)
            acc = fmaf(h1[j], W2[p * (M1 * M2) + j * M2 + m], acc);
        float g = tanhf(acc) + h1[m % M1];
        g_table[(p * KNOT + i) * M2 + m] = g;
    }
}

// ---- main: per-(b,n) CTA, table-driven, no inner barriers ----
__global__ __launch_bounds__(TPB) void main_kernel(
    const float* __restrict__ coords, const int* __restrict__ types,
    float* __restrict__ out)
{
    __shared__ float Sred[5][M2 * 3];
    __shared__ float Sfin[M2 * 3];

    int t = threadIdx.x;
    int bid = blockIdx.x;
    int n = bid % NATOM;
    int b = bid / NATOM;
    int tc = __ldg(&types[n]);
    float cx = __ldg(&coords[(b * NATOM + n) * 3 + 0]);
    float cy = __ldg(&coords[(b * NATOM + n) * 3 + 1]);
    float cz = __ldg(&coords[(b * NATOM + n) * 3 + 2]);

    int ipos = __ldg(&g_ipos[n]);
    int nbs[NT + 1];
#pragma unroll
    for (int c = 0; c <= NT; c++) {
        int sg = __ldg(&g_start[c]);
        nbs[c] = sg - (sg > ipos ? 1 : 0);
    }

    int mi = t % 25;          // m-quad index: owns m = mi*4 .. mi*4+3
    int ge = t / 25;          // edge group 0..4
    bool act = (t < 125);

    float4 S0 = make_float4(0.f, 0.f, 0.f, 0.f);   // c=0 over m-quad
    float4 S1 = make_float4(0.f, 0.f, 0.f, 0.f);   // c=1
    float4 S2 = make_float4(0.f, 0.f, 0.f, 0.f);   // c=2

    if (act) {
        for (int tn = 0; tn < NT; tn++) {
            int pair = tc * NT + tn;
            const float* tb = g_table + (size_t)pair * (KNOT * M2) + mi * 4;
            int bs = nbs[tn], en = nbs[tn + 1];
            for (int k = bs + ge; k < en; k += 5) {
                int j = __ldg(&g_sorted[k + (k >= ipos ? 1 : 0)]);
                float rx = cx - __ldg(&coords[(b * NATOM + j) * 3 + 0]);
                float ry = cy - __ldg(&coords[(b * NATOM + j) * 3 + 1]);
                float rz = cz - __ldg(&coords[(b * NATOM + j) * 3 + 2]);
                float d2 = rx * rx + ry * ry + rz * rz;
                float x = rsqrtf(d2);          // 1/d
                float i2 = x * x;
                float ax = rx * i2, ay = ry * i2, az = rz * i2;

                float u = __fdividef(x, x + CWARP);
                float pos = u * (float)(KNOT - 1);
                int i1 = (int)pos;
                i1 = min(i1, KNOT - 2);
                float fr = pos - (float)i1;
                int i0 = max(i1 - 1, 0);
                int i2k = i1 + 1;
                int i3 = min(i1 + 2, KNOT - 1);

                float fr2 = fr * fr, fr3 = fr2 * fr;
                float w0 = -0.5f * fr3 + fr2 - 0.5f * fr;
                float w1 = 1.5f * fr3 - 2.5f * fr2 + 1.0f;
                float w2 = -1.5f * fr3 + 2.0f * fr2 + 0.5f * fr;
                float w3 = 0.5f * fr3 - 0.5f * fr2;

                float4 f0 = *(const float4*)(tb + i0 * M2);
                float4 f1 = *(const float4*)(tb + i1 * M2);
                float4 f2 = *(const float4*)(tb + i2k * M2);
                float4 f3 = *(const float4*)(tb + i3 * M2);

                float4 G;
                G.x = fmaf(w0, f0.x, fmaf(w1, f1.x, fmaf(w2, f2.x, w3 * f3.x)));
                G.y = fmaf(w0, f0.y, fmaf(w1, f1.y, fmaf(w2, f2.y, w3 * f3.y)));
                G.z = fmaf(w0, f0.z, fmaf(w1, f1.z, fmaf(w2, f2.z, w3 * f3.z)));
                G.w = fmaf(w0, f0.w, fmaf(w1, f1.w, fmaf(w2, f2.w, w3 * f3.w)));

                S0.x = fmaf(ax, G.x, S0.x); S0.y = fmaf(ax, G.y, S0.y);
                S0.z = fmaf(ax, G.z, S0.z); S0.w = fmaf(ax, G.w, S0.w);
                S1.x = fmaf(ay, G.x, S1.x); S1.y = fmaf(ay, G.y, S1.y);
                S1.z = fmaf(ay, G.z, S1.z); S1.w = fmaf(ay, G.w, S1.w);
                S2.x = fmaf(az, G.x, S2.x); S2.y = fmaf(az, G.y, S2.y);
                S2.z = fmaf(az, G.z, S2.z); S2.w = fmaf(az, G.w, S2.w);
            }
        }
    }

    // ---- reduce across edge groups ----
    if (act) {
        int mb = mi * 4;
        Sred[ge][(mb + 0) * 3 + 0] = S0.x; Sred[ge][(mb + 0) * 3 + 1] = S1.x; Sred[ge][(mb + 0) * 3 + 2] = S2.x;
        Sred[ge][(mb + 1) * 3 + 0] = S0.y; Sred[ge][(mb + 1) * 3 + 1] = S1.y; Sred[ge][(mb + 1) * 3 + 2] = S2.y;
        Sred[ge][(mb + 2) * 3 + 0] = S0.z; Sred[ge][(mb + 2) * 3 + 1] = S1.z; Sred[ge][(mb + 2) * 3 + 2] = S2.z;
        Sred[ge][(mb + 3) * 3 + 0] = S0.w; Sred[ge][(mb + 3) * 3 + 1] = S1.w; Sred[ge][(mb + 3) * 3 + 2] = S2.w;
    }
    __syncthreads();
    if (t < M2) {
        float s0 = 0.f, s1 = 0.f, s2 = 0.f;
#pragma unroll
        for (int g = 0; g < 5; g++) {
            s0 += Sred[g][t * 3 + 0];
            s1 += Sred[g][t * 3 + 1];
            s2 += Sred[g][t * 3 + 2];
        }
        Sfin[t * 3 + 0] = s0; Sfin[t * 3 + 1] = s1; Sfin[t * 3 + 2] = s2;
    }
    __syncthreads();
    if (t < M2) {
        float s0 = Sfin[t * 3 + 0], s1 = Sfin[t * 3 + 1], s2 = Sfin[t * 3 + 2];
        float4 o;
        o.x = s0 * Sfin[0] + s1 * Sfin[1] + s2 * Sfin[2];
        o.y = s0 * Sfin[3] + s1 * Sfin[4] + s2 * Sfin[5];
        o.z = s0 * Sfin[6] + s1 * Sfin[7] + s2 * Sfin[8];
        o.w = s0 * Sfin[9] + s1 * Sfin[10] + s2 * Sfin[11];
        *(float4*)(out + (size_t)bid * (M2 * 4) + t * 4) = o;
    }
}

extern "C" void kernel_launch(void* const* d_in, const int* in_sizes, int n_in,
                              void* d_out, int out_size)
{
    const float* coords = (const float*)d_in[0];
    const int*   types  = (const int*)d_in[1];
    const float* W0     = (const float*)d_in[2];
    const float* b0     = (const float*)d_in[3];
    const float* W1     = (const float*)d_in[4];
    const float* b1     = (const float*)d_in[5];
    const float* W2     = (const float*)d_in[6];
    const float* b2     = (const float*)d_in[7];
    float* out = (float*)d_out;

    prep_kernel<<<1, NATOM>>>(types);
    build_kernel<<<16 * KNOT, M2>>>(W0, b0, W1, b1, W2, b2);
    main_kernel<<<NB * NATOM, TPB>>>(coords, types, out);
}

// round 16
// speedup vs baseline: 4.1126x; 1.0673x over previous
#include <cuda_runtime.h>
#include <math.h>

#define NATOM 384
#define NB 8
#define KNBR 383
#define NT 4
#define M0 25
#define M1 50
#define M2 100
#define TPB 128
#define KNOT 1024
#define BK 4                    // knots per build block
#define GRID_BUILD (16 * KNOT / BK)   // 4096 build blocks (+1 prep block)
#define CWARP 0.25f

__device__ int g_sorted[NATOM];
__device__ int g_ipos[NATOM];
__device__ int g_start[NT + 1];
__device__ float g_table[16 * KNOT * M2];   // 6.55 MB

// ---- fused build + prep: blocks [0, GRID_BUILD) build the table;
//      block GRID_BUILD does the type sort (bitmask popc). blockDim = 400.
__global__ void build_kernel(
    const float* __restrict__ W0, const float* __restrict__ b0,
    const float* __restrict__ W1, const float* __restrict__ b1,
    const float* __restrict__ W2, const float* __restrict__ b2,
    const int* __restrict__ types)
{
    int t = threadIdx.x;

    if (blockIdx.x == GRID_BUILD) {
        // ---- prep: stable counting sort by (type, index) via bitmasks ----
        __shared__ unsigned tm[NT][12];   // 384 bits per type
        if (t < NT * 12) ((unsigned*)tm)[t] = 0u;
        __syncthreads();
        int c = 0;
        if (t < NATOM) {
            c = __ldg(&types[t]);
            atomicOr(&tm[c][t >> 5], 1u << (t & 31));
        }
        __syncthreads();
        if (t < NATOM) {
            int cnt0 = 0, cnt1 = 0, cnt2 = 0;
#pragma unroll
            for (int w = 0; w < 12; w++) {
                cnt0 += __popc(tm[0][w]);
                cnt1 += __popc(tm[1][w]);
                cnt2 += __popc(tm[2][w]);
            }
            int s1 = cnt0, s2 = cnt0 + cnt1, s3 = cnt0 + cnt1 + cnt2;
            int base = (c == 0) ? 0 : (c == 1) ? s1 : (c == 2) ? s2 : s3;
            int rank = 0;
            int tw = t >> 5;
            for (int w = 0; w < tw; w++) rank += __popc(tm[c][w]);
            rank += __popc(tm[c][tw] & ((1u << (t & 31)) - 1u));
            int pos = base + rank;
            g_sorted[pos] = t;
            g_ipos[t] = pos;
            if (t == 0) {
                g_start[0] = 0; g_start[1] = s1; g_start[2] = s2; g_start[3] = s3;
                g_start[4] = NATOM;
            }
        }
        return;
    }

    // ---- table build: 4 knots per block, 100 threads per knot ----
    int sub = t / M2;            // 0..3
    int m = t - sub * M2;        // 0..99
    int kid = blockIdx.x * BK + sub;
    int p = kid / KNOT;
    int i = kid - p * KNOT;

    float u = (float)i / (float)(KNOT - 1);
    u = fminf(u, 0.9999f);
    float x = CWARP * u / (1.0f - u);

    __shared__ float h0[BK][M0];
    __shared__ float h1[BK][M1];

    if (m < M0)
        h0[sub][m] = tanhf(x * W0[p * M0 + m] + b0[p * M0 + m]);
    __syncthreads();
    if (m < M1) {
        float acc = b1[p * M1 + m];
        for (int j = 0; j < M0; j++)
            acc = fmaf(h0[sub][j], W1[p * (M0 * M1) + j * M1 + m], acc);
        h1[sub][m] = tanhf(acc) + h0[sub][m % M0];
    }
    __syncthreads();
    {
        float acc = b2[p * M2 + m];
        for (int j = 0; j < M1; j++)
            acc = fmaf(h1[sub][j], W2[p * (M1 * M2) + j * M2 + m], acc);
        float g = tanhf(acc) + h1[sub][m % M1];
        g_table[(size_t)(p * KNOT + i) * M2 + m] = g;
    }
}

// ---- main: per-(b,n) CTA, table-driven linear interp, no inner barriers ----
__global__ __launch_bounds__(TPB) void main_kernel(
    const float* __restrict__ coords, const int* __restrict__ types,
    float* __restrict__ out)
{
    __shared__ float Sred[5][M2 * 3];
    __shared__ float Sfin[M2 * 3];

    int t = threadIdx.x;
    int bid = blockIdx.x;
    int n = bid % NATOM;
    int b = bid / NATOM;
    int tc = __ldg(&types[n]);
    float cx = __ldg(&coords[(b * NATOM + n) * 3 + 0]);
    float cy = __ldg(&coords[(b * NATOM + n) * 3 + 1]);
    float cz = __ldg(&coords[(b * NATOM + n) * 3 + 2]);

    int ipos = __ldg(&g_ipos[n]);
    int nbs[NT + 1];
#pragma unroll
    for (int c = 0; c <= NT; c++) {
        int sg = __ldg(&g_start[c]);
        nbs[c] = sg - (sg > ipos ? 1 : 0);
    }

    int mi = t % 25;          // owns m = mi*4 .. mi*4+3
    int ge = t / 25;          // edge group 0..4
    bool act = (t < 125);

    float4 S0 = make_float4(0.f, 0.f, 0.f, 0.f);
    float4 S1 = make_float4(0.f, 0.f, 0.f, 0.f);
    float4 S2 = make_float4(0.f, 0.f, 0.f, 0.f);

    if (act) {
        for (int tn = 0; tn < NT; tn++) {
            int pair = tc * NT + tn;
            const float* tb = g_table + (size_t)pair * (KNOT * M2) + mi * 4;
            int bs = nbs[tn], en = nbs[tn + 1];
            for (int k = bs + ge; k < en; k += 5) {
                int j = __ldg(&g_sorted[k + (k >= ipos ? 1 : 0)]);
                float rx = cx - __ldg(&coords[(b * NATOM + j) * 3 + 0]);
                float ry = cy - __ldg(&coords[(b * NATOM + j) * 3 + 1]);
                float rz = cz - __ldg(&coords[(b * NATOM + j) * 3 + 2]);
                float d2 = rx * rx + ry * ry + rz * rz;
                float x = rsqrtf(d2);
                float i2 = x * x;
                float ax = rx * i2, ay = ry * i2, az = rz * i2;

                float u = __fdividef(x, x + CWARP);
                float pos = u * (float)(KNOT - 1);
                int i0 = (int)pos;
                i0 = min(i0, KNOT - 2);
                float fr = pos - (float)i0;

                float4 f0 = *(const float4*)(tb + i0 * M2);
                float4 f1 = *(const float4*)(tb + (i0 + 1) * M2);

                float4 G;
                G.x = fmaf(fr, f1.x - f0.x, f0.x);
                G.y = fmaf(fr, f1.y - f0.y, f0.y);
                G.z = fmaf(fr, f1.z - f0.z, f0.z);
                G.w = fmaf(fr, f1.w - f0.w, f0.w);

                S0.x = fmaf(ax, G.x, S0.x); S0.y = fmaf(ax, G.y, S0.y);
                S0.z = fmaf(ax, G.z, S0.z); S0.w = fmaf(ax, G.w, S0.w);
                S1.x = fmaf(ay, G.x, S1.x); S1.y = fmaf(ay, G.y, S1.y);
                S1.z = fmaf(ay, G.z, S1.z); S1.w = fmaf(ay, G.w, S1.w);
                S2.x = fmaf(az, G.x, S2.x); S2.y = fmaf(az, G.y, S2.y);
                S2.z = fmaf(az, G.z, S2.z); S2.w = fmaf(az, G.w, S2.w);
            }
        }
    }

    // ---- reduce across edge groups ----
    if (act) {
        int mb = mi * 4;
        Sred[ge][(mb + 0) * 3 + 0] = S0.x; Sred[ge][(mb + 0) * 3 + 1] = S1.x; Sred[ge][(mb + 0) * 3 + 2] = S2.x;
        Sred[ge][(mb + 1) * 3 + 0] = S0.y; Sred[ge][(mb + 1) * 3 + 1] = S1.y; Sred[ge][(mb + 1) * 3 + 2] = S2.y;
        Sred[ge][(mb + 2) * 3 + 0] = S0.z; Sred[ge][(mb + 2) * 3 + 1] = S1.z; Sred[ge][(mb + 2) * 3 + 2] = S2.z;
        Sred[ge][(mb + 3) * 3 + 0] = S0.w; Sred[ge][(mb + 3) * 3 + 1] = S1.w; Sred[ge][(mb + 3) * 3 + 2] = S2.w;
    }
    __syncthreads();
    if (t < M2) {
        float s0 = 0.f, s1 = 0.f, s2 = 0.f;
#pragma unroll
        for (int g = 0; g < 5; g++) {
            s0 += Sred[g][t * 3 + 0];
            s1 += Sred[g][t * 3 + 1];
            s2 += Sred[g][t * 3 + 2];
        }
        Sfin[t * 3 + 0] = s0; Sfin[t * 3 + 1] = s1; Sfin[t * 3 + 2] = s2;
    }
    __syncthreads();
    if (t < M2) {
        float s0 = Sfin[t * 3 + 0], s1 = Sfin[t * 3 + 1], s2 = Sfin[t * 3 + 2];
        float4 o;
        o.x = s0 * Sfin[0] + s1 * Sfin[1] + s2 * Sfin[2];
        o.y = s0 * Sfin[3] + s1 * Sfin[4] + s2 * Sfin[5];
        o.z = s0 * Sfin[6] + s1 * Sfin[7] + s2 * Sfin[8];
        o.w = s0 * Sfin[9] + s1 * Sfin[10] + s2 * Sfin[11];
        *(float4*)(out + (size_t)bid * (M2 * 4) + t * 4) = o;
    }
}

extern "C" void kernel_launch(void* const* d_in, const int* in_sizes, int n_in,
                              void* d_out, int out_size)
{
    const float* coords = (const float*)d_in[0];
    const int*   types  = (const int*)d_in[1];
    const float* W0     = (const float*)d_in[2];
    const float* b0     = (const float*)d_in[3];
    const float* W1     = (const float*)d_in[4];
    const float* b1     = (const float*)d_in[5];
    const float* W2     = (const float*)d_in[6];
    const float* b2     = (const float*)d_in[7];
    float* out = (float*)d_out;

    build_kernel<<<GRID_BUILD + 1, 400>>>(W0, b0, W1, b1, W2, b2, types);
    main_kernel<<<NB * NATOM, TPB>>>(coords, types, out);
}

// round 17
// speedup vs baseline: 5.4106x; 1.3156x over previous
#include <cuda_runtime.h>
#include <math.h>

#define NATOM 384
#define NB 8
#define KNBR 383
#define NT 4
#define M0 25
#define M1 50
#define M2 100
#define TPB 128
#define KNOT 1024
#define BK 4
#define GRID_BUILD (16 * KNOT / BK)
#define CWARP 0.25f

__device__ int g_sorted[NATOM];
__device__ int g_ipos[NATOM];
__device__ int g_start[NT + 1];
__device__ float g_table[16 * KNOT * M2];   // 6.55 MB

// ---- fused build + prep ----
__global__ void build_kernel(
    const float* __restrict__ W0, const float* __restrict__ b0,
    const float* __restrict__ W1, const float* __restrict__ b1,
    const float* __restrict__ W2, const float* __restrict__ b2,
    const int* __restrict__ types)
{
    int t = threadIdx.x;

    if (blockIdx.x == GRID_BUILD) {
        __shared__ unsigned tm[NT][12];
        if (t < NT * 12) ((unsigned*)tm)[t] = 0u;
        __syncthreads();
        int c = 0;
        if (t < NATOM) {
            c = __ldg(&types[t]);
            atomicOr(&tm[c][t >> 5], 1u << (t & 31));
        }
        __syncthreads();
        if (t < NATOM) {
            int cnt0 = 0, cnt1 = 0, cnt2 = 0;
#pragma unroll
            for (int w = 0; w < 12; w++) {
                cnt0 += __popc(tm[0][w]);
                cnt1 += __popc(tm[1][w]);
                cnt2 += __popc(tm[2][w]);
            }
            int s1 = cnt0, s2 = cnt0 + cnt1, s3 = cnt0 + cnt1 + cnt2;
            int base = (c == 0) ? 0 : (c == 1) ? s1 : (c == 2) ? s2 : s3;
            int rank = 0;
            int tw = t >> 5;
            for (int w = 0; w < tw; w++) rank += __popc(tm[c][w]);
            rank += __popc(tm[c][tw] & ((1u << (t & 31)) - 1u));
            int pos = base + rank;
            g_sorted[pos] = t;
            g_ipos[t] = pos;
            if (t == 0) {
                g_start[0] = 0; g_start[1] = s1; g_start[2] = s2; g_start[3] = s3;
                g_start[4] = NATOM;
            }
        }
        return;
    }

    int sub = t / M2;
    int m = t - sub * M2;
    int kid = blockIdx.x * BK + sub;
    int p = kid / KNOT;
    int i = kid - p * KNOT;

    float u = (float)i / (float)(KNOT - 1);
    u = fminf(u, 0.9999f);
    float x = CWARP * u / (1.0f - u);

    __shared__ float h0[BK][M0];
    __shared__ float h1[BK][M1];

    if (m < M0)
        h0[sub][m] = tanhf(x * W0[p * M0 + m] + b0[p * M0 + m]);
    __syncthreads();
    if (m < M1) {
        float acc = b1[p * M1 + m];
        for (int j = 0; j < M0; j++)
            acc = fmaf(h0[sub][j], W1[p * (M0 * M1) + j * M1 + m], acc);
        h1[sub][m] = tanhf(acc) + h0[sub][m % M0];
    }
    __syncthreads();
    {
        float acc = b2[p * M2 + m];
        for (int j = 0; j < M1; j++)
            acc = fmaf(h1[sub][j], W2[p * (M1 * M2) + j * M2 + m], acc);
        float g = tanhf(acc) + h1[sub][m % M1];
        g_table[(size_t)(p * KNOT + i) * M2 + m] = g;
    }
}

// ---- main: coords staged in smem (sorted order), table linear interp ----
__global__ __launch_bounds__(TPB) void main_kernel(
    const float* __restrict__ coords, const int* __restrict__ types,
    float* __restrict__ out)
{
    __shared__ float4 cs[NATOM];        // coords in sorted position
    __shared__ float Sred[5][M2 * 3];
    __shared__ float Sfin[M2 * 3];

    int t = threadIdx.x;
    int bid = blockIdx.x;
    int n = bid % NATOM;
    int b = bid / NATOM;
    int tc = __ldg(&types[n]);

    // stage coords (coalesced global reads, permuted smem writes)
    for (int a = t; a < NATOM; a += TPB) {
        float x = __ldg(&coords[(b * NATOM + a) * 3 + 0]);
        float y = __ldg(&coords[(b * NATOM + a) * 3 + 1]);
        float z = __ldg(&coords[(b * NATOM + a) * 3 + 2]);
        cs[__ldg(&g_ipos[a])] = make_float4(x, y, z, 0.f);
    }

    int ipos = __ldg(&g_ipos[n]);
    int nbs[NT + 1];
#pragma unroll
    for (int c = 0; c <= NT; c++) {
        int sg = __ldg(&g_start[c]);
        nbs[c] = sg - (sg > ipos ? 1 : 0);
    }

    __syncthreads();

    float cx = cs[ipos].x, cy = cs[ipos].y, cz = cs[ipos].z;

    int mi = t % 25;
    int ge = t / 25;
    bool act = (t < 125);

    float4 S0 = make_float4(0.f, 0.f, 0.f, 0.f);
    float4 S1 = make_float4(0.f, 0.f, 0.f, 0.f);
    float4 S2 = make_float4(0.f, 0.f, 0.f, 0.f);

    if (act) {
        for (int tn = 0; tn < NT; tn++) {
            int pair = tc * NT + tn;
            const float* tb = g_table + (size_t)pair * (KNOT * M2) + mi * 4;
            int bs = nbs[tn], en = nbs[tn + 1];
#pragma unroll 4
            for (int k = bs + ge; k < en; k += 5) {
                float4 cj = cs[k + (k >= ipos ? 1 : 0)];
                float rx = cx - cj.x;
                float ry = cy - cj.y;
                float rz = cz - cj.z;
                float d2 = rx * rx + ry * ry + rz * rz;
                float x = rsqrtf(d2);
                float i2 = x * x;
                float ax = rx * i2, ay = ry * i2, az = rz * i2;

                float u = __fdividef(x, x + CWARP);
                float pos = u * (float)(KNOT - 1);
                int i0 = (int)pos;
                i0 = min(i0, KNOT - 2);
                float fr = pos - (float)i0;

                float4 f0 = __ldg((const float4*)(tb + i0 * M2));
                float4 f1 = __ldg((const float4*)(tb + (i0 + 1) * M2));

                float4 G;
                G.x = fmaf(fr, f1.x - f0.x, f0.x);
                G.y = fmaf(fr, f1.y - f0.y, f0.y);
                G.z = fmaf(fr, f1.z - f0.z, f0.z);
                G.w = fmaf(fr, f1.w - f0.w, f0.w);

                S0.x = fmaf(ax, G.x, S0.x); S0.y = fmaf(ax, G.y, S0.y);
                S0.z = fmaf(ax, G.z, S0.z); S0.w = fmaf(ax, G.w, S0.w);
                S1.x = fmaf(ay, G.x, S1.x); S1.y = fmaf(ay, G.y, S1.y);
                S1.z = fmaf(ay, G.z, S1.z); S1.w = fmaf(ay, G.w, S1.w);
                S2.x = fmaf(az, G.x, S2.x); S2.y = fmaf(az, G.y, S2.y);
                S2.z = fmaf(az, G.z, S2.z); S2.w = fmaf(az, G.w, S2.w);
            }
        }
    }

    // ---- reduce across edge groups ----
    if (act) {
        int mb = mi * 4;
        Sred[ge][(mb + 0) * 3 + 0] = S0.x; Sred[ge][(mb + 0) * 3 + 1] = S1.x; Sred[ge][(mb + 0) * 3 + 2] = S2.x;
        Sred[ge][(mb + 1) * 3 + 0] = S0.y; Sred[ge][(mb + 1) * 3 + 1] = S1.y; Sred[ge][(mb + 1) * 3 + 2] = S2.y;
        Sred[ge][(mb + 2) * 3 + 0] = S0.z; Sred[ge][(mb + 2) * 3 + 1] = S1.z; Sred[ge][(mb + 2) * 3 + 2] = S2.z;
        Sred[ge][(mb + 3) * 3 + 0] = S0.w; Sred[ge][(mb + 3) * 3 + 1] = S1.w; Sred[ge][(mb + 3) * 3 + 2] = S2.w;
    }
    __syncthreads();
    if (t < M2) {
        float s0 = 0.f, s1 = 0.f, s2 = 0.f;
#pragma unroll
        for (int g = 0; g < 5; g++) {
            s0 += Sred[g][t * 3 + 0];
            s1 += Sred[g][t * 3 + 1];
            s2 += Sred[g][t * 3 + 2];
        }
        Sfin[t * 3 + 0] = s0; Sfin[t * 3 + 1] = s1; Sfin[t * 3 + 2] = s2;
    }
    __syncthreads();
    if (t < M2) {
        float s0 = Sfin[t * 3 + 0], s1 = Sfin[t * 3 + 1], s2 = Sfin[t * 3 + 2];
        float4 o;
        o.x = s0 * Sfin[0] + s1 * Sfin[1] + s2 * Sfin[2];
        o.y = s0 * Sfin[3] + s1 * Sfin[4] + s2 * Sfin[5];
        o.z = s0 * Sfin[6] + s1 * Sfin[7] + s2 * Sfin[8];
        o.w = s0 * Sfin[9] + s1 * Sfin[10] + s2 * Sfin[11];
        *(float4*)(out + (size_t)bid * (M2 * 4) + t * 4) = o;
    }
}

extern "C" void kernel_launch(void* const* d_in, const int* in_sizes, int n_in,
                              void* d_out, int out_size)
{
    const float* coords = (const float*)d_in[0];
    const int*   types  = (const int*)d_in[1];
    const float* W0     = (const float*)d_in[2];
    const float* b0     = (const float*)d_in[3];
    const float* W1     = (const float*)d_in[4];
    const float* b1     = (const float*)d_in[5];
    const float* W2     = (const float*)d_in[6];
    const float* b2     = (const float*)d_in[7];
    float* out = (float*)d_out;

    build_kernel<<<GRID_BUILD + 1, 400>>>(W0, b0, W1, b1, W2, b2, types);
    main_kernel<<<NB * NATOM, TPB>>>(coords, types, out);
}